// round 1
// baseline (speedup 1.0000x reference)
#include <cuda_runtime.h>
#include <cstdint>

// Problem constants
#define T_LEN   730
#define B_LEN   1000
#define NMUL    8
#define LENF    15
#define NEARZERO 1e-5f

// Scratch (device globals: allocation-free)
__device__ float g_qsim [T_LEN * B_LEN];
__device__ float g_qsurf[T_LEN * B_LEN];
__device__ float g_qgw  [T_LEN * B_LEN];
__device__ float g_uh   [B_LEN * LENF];

__device__ __forceinline__ float f_sqrt_approx(float x) {
    float r;
    asm("sqrt.approx.f32 %0, %1;" : "=f"(r) : "f"(x));
    return r;
}
__device__ __forceinline__ float f_ex2(float x) {
    float r;
    asm("ex2.approx.f32 %0, %1;" : "=f"(r) : "f"(x));
    return r;
}
__device__ __forceinline__ float rsum8(float v) {
    v += __shfl_xor_sync(0xffffffffu, v, 1);
    v += __shfl_xor_sync(0xffffffffu, v, 2);
    v += __shfl_xor_sync(0xffffffffu, v, 4);
    return v;
}

// ---------------------------------------------------------------------------
// Kernel 1: gamma unit hydrograph weights, one thread per basin
// ---------------------------------------------------------------------------
__global__ void uh_kernel(const float* __restrict__ raw) {
    int b = blockIdx.x * blockDim.x + threadIdx.x;
    if (b >= B_LEN) return;
    float ra = raw[b * 34 + 32] * 2.9f;   // RA_LO=0, RA_HI=2.9
    float rb = raw[b * 34 + 33] * 6.5f;   // RB_LO=0, RB_HI=6.5
    float aa    = fmaxf(ra, 0.0f) + 0.1f;
    float theta = fmaxf(rb, 0.0f) + 0.5f;
    float lg   = lgammaf(aa);
    float lth  = logf(theta);
    float ivth = 1.0f / theta;
    float w[LENF];
    float s = 0.0f;
#pragma unroll
    for (int k = 0; k < LENF; ++k) {
        float t = (float)k + 0.5f;
        float lw = (aa - 1.0f) * logf(t) - t * ivth - lg - aa * lth;
        w[k] = expf(lw);
        s += w[k];
    }
    float inv = 1.0f / s;
#pragma unroll
    for (int k = 0; k < LENF; ++k)
        g_uh[b * LENF + k] = w[k] * inv;
}

// ---------------------------------------------------------------------------
// Kernel 2: the sequential abcd scan. 8000 threads, one chain per thread.
// 8 lanes = 8 NMUL channels of one basin; butterfly-reduce means in-warp.
// Lanes 0..5 each own one output column (distributed single STG per iter).
// ---------------------------------------------------------------------------
#define UG 10          // timesteps per prefetch group (730 = 73*10)
#define NGROUPS 73

__global__ void __launch_bounds__(64, 4) scan_kernel(
    const float* __restrict__ x,      // (T,B,2)
    const float* __restrict__ raw,    // (B,34)
    float* __restrict__ out)          // (T,B,6)
{
    int g  = blockIdx.x * 64 + threadIdx.x;   // 0..7999
    int b  = g >> 3;
    int m  = g & 7;

    // per-chain parameters
    float r0 = raw[b * 34 +      m];
    float r1 = raw[b * 34 +  8 + m];
    float r2 = raw[b * 34 + 16 + m];
    float r3 = raw[b * 34 + 24 + m];
    float a   = fmaf(r0, 0.9f, 0.1f);
    float bb  = fmaf(r1, 450.0f, 50.0f);
    float c   = r2;
    float d   = fmaf(r3, 0.89f, 0.01f);

    float inv2a    = 0.5f / a;
    float binv2a   = bb * inv2a;
    float boa      = bb / a;
    float nl2eob   = -1.44269504088896f / bb;   // -log2(e)/b
    float onemc    = 1.0f - c;
    float inv1pd   = 1.0f / (1.0f + d);

    float S = 50.0f, G = 10.0f;

    // per-lane output routing (loop-invariant)
    bool is1 = (m == 1), is2 = (m == 2), is3 = (m == 3), is4 = (m == 4), is5 = (m == 5);
    bool doStore = (m < 6);
    float* sp;
    int sstride;
    if      (m == 0) { sp = g_qsim  + b;           sstride = B_LEN; }
    else if (m == 1) { sp = g_qsurf + b;           sstride = B_LEN; }
    else if (m == 2) { sp = g_qgw   + b;           sstride = B_LEN; }
    else if (m == 3) { sp = out + b * 6 + 3;       sstride = 6 * B_LEN; }
    else if (m == 4) { sp = out + b * 6 + 4;       sstride = 6 * B_LEN; }
    else if (m == 5) { sp = out + b * 6 + 5;       sstride = 6 * B_LEN; }
    else             { sp = g_qsim + b;            sstride = B_LEN; }  // inert

    const float2* __restrict__ xv = (const float2*)x;   // index t*B + b

    float2 cur[UG], nxt[UG];
#pragma unroll
    for (int i = 0; i < UG; ++i) cur[i] = __ldg(xv + i * B_LEN + b);

    for (int gi = 0; gi < NGROUPS; ++gi) {
        if (gi < NGROUPS - 1) {
            const float2* base = xv + (gi + 1) * UG * B_LEN + b;
#pragma unroll
            for (int i = 0; i < UG; ++i) nxt[i] = __ldg(base + i * B_LEN);
        }
#pragma unroll
        for (int i = 0; i < UG; ++i) {
            float p   = cur[i].x;
            float pet = cur[i].y;

            float W    = p + S;
            float term = fmaf(W, inv2a, binv2a);
            float wboa = W * boa;
            float arg  = fmaf(term, term, -wboa);
            arg        = fmaxf(arg, NEARZERO);
            float sq   = f_sqrt_approx(arg);
            float Y    = term - sq;
            float ef   = f_ex2(pet * nl2eob);
            float Snew = Y * ef;
            float avail = W - Y;
            float Qsurf = onemc * avail;
            float Gnew  = fmaf(c, avail, G) * inv1pd;
            float Qgw   = d * Gnew;
            S = Snew;
            G = Gnew;

            float Ss  = rsum8(Snew);
            float Gs  = rsum8(Gnew);
            float Ys  = rsum8(Y);
            float Qss = rsum8(Qsurf);
            float Qgs = rsum8(Qgw);

            float v = Qss + Qgs;              // m==0: Qsim sum
            if (is1) v = Qss;
            if (is2) v = Qgs;
            if (is3) v = Ys - Ss;             // AET sum
            if (is4) v = Ss;
            if (is5) v = Gs;
            v *= 0.125f;                      // mean over NMUL=8
            if (doStore) *sp = v;
            sp += sstride;
        }
        if (gi < NGROUPS - 1) {
#pragma unroll
            for (int i = 0; i < UG; ++i) cur[i] = nxt[i];
        }
    }
}

// ---------------------------------------------------------------------------
// Kernel 3: causal 15-tap convolution. Each thread produces 5 consecutive t
// for one basin, all three routed series. 730 = 146*5.
// ---------------------------------------------------------------------------
#define TPER 5
__global__ void conv_kernel(float* __restrict__ out) {
    int idx = blockIdx.x * blockDim.x + threadIdx.x;
    if (idx >= (T_LEN / TPER) * B_LEN) return;
    int b    = idx % B_LEN;
    int t0   = (idx / B_LEN) * TPER;

    float uh[LENF];
#pragma unroll
    for (int k = 0; k < LENF; ++k) uh[k] = __ldg(&g_uh[b * LENF + k]);

    const float* srcs[3] = { g_qsim, g_qsurf, g_qgw };
#pragma unroll
    for (int s = 0; s < 3; ++s) {
        const float* __restrict__ q = srcs[s];
        float qs[LENF - 1 + TPER];           // times t0-14 .. t0+4
#pragma unroll
        for (int i = 0; i < LENF - 1 + TPER; ++i) {
            int tt = t0 - (LENF - 1) + i;
            qs[i] = (tt >= 0) ? __ldg(&q[tt * B_LEN + b]) : 0.0f;
        }
#pragma unroll
        for (int j = 0; j < TPER; ++j) {
            float acc = 0.0f;
#pragma unroll
            for (int k = 0; k < LENF; ++k)
                acc = fmaf(uh[k], qs[LENF - 1 + j - k], acc);
            out[(t0 + j) * (6 * B_LEN) + b * 6 + s] = acc;
        }
    }
}

// ---------------------------------------------------------------------------
extern "C" void kernel_launch(void* const* d_in, const int* in_sizes, int n_in,
                              void* d_out, int out_size) {
    const float* x   = (const float*)d_in[0];   // (730,1000,2)
    const float* raw = (const float*)d_in[1];   // (1000,34)
    float* out = (float*)d_out;                 // (730,1000,6)

    uh_kernel<<<(B_LEN + 255) / 256, 256>>>(raw);
    scan_kernel<<<(B_LEN * NMUL) / 64, 64>>>(x, raw, out);
    int nconv = (T_LEN / TPER) * B_LEN;
    conv_kernel<<<(nconv + 255) / 256, 256>>>(out);
}